// round 14
// baseline (speedup 1.0000x reference)
#include <cuda_runtime.h>
#include <cuda_fp16.h>
#include <cstdint>

#define HW_   56
#define C_    128
#define F_    128
#define B_    32
#define PIX_  (HW_*HW_)
#define XHW   58                 // padded spatial
#define STAGE 32768              // A 16KB + B 16KB (halves, K=64 per step)
#define NST   2
#define DYN   (NST*STAGE + 1024)

// device scratch (static globals = allowed)
__device__ __half g_xh[(size_t)B_ * XHW * XHW * C_];  // [b][hp][wp][c] fp16, zero halo
__device__ __half g_wt[18 * 128 * 64];                // [tap*2+hc][f][c(64)] fp16

__device__ __forceinline__ uint32_t smem_u32(const void* p) {
    uint32_t a;
    asm("{ .reg .u64 t; cvta.to.shared.u64 t, %1; cvt.u32.u64 %0, t; }" : "=r"(a) : "l"(p));
    return a;
}
__device__ __forceinline__ void mma_f16(float d[4], const uint32_t a[4], const uint32_t b[2]) {
    asm volatile(
        "mma.sync.aligned.m16n8k16.row.col.f32.f16.f16.f32 "
        "{%0,%1,%2,%3}, {%4,%5,%6,%7}, {%8,%9}, {%0,%1,%2,%3};\n"
        : "+f"(d[0]), "+f"(d[1]), "+f"(d[2]), "+f"(d[3])
        : "r"(a[0]), "r"(a[1]), "r"(a[2]), "r"(a[3]), "r"(b[0]), "r"(b[1]));
}
#define LDSM4(r0, r1, r2, r3, a) \
    asm volatile("ldmatrix.sync.aligned.m8n8.x4.shared.b16 {%0,%1,%2,%3}, [%4];" \
                 : "=r"(r0), "=r"(r1), "=r"(r2), "=r"(r3) : "r"(a))
#define CP_CG(d, s) asm volatile("cp.async.cg.shared.global [%0], [%1], 16;" :: "r"(d), "l"(s))
#define CP_CA(d, s) asm volatile("cp.async.ca.shared.global [%0], [%1], 16;" :: "r"(d), "l"(s))
#define CP_COMMIT() asm volatile("cp.async.commit_group;" ::: "memory")

// ---------- prologue 1: x NCHW fp32 -> zero-padded NHWC fp16 (R10 config) ----------
__global__ __launch_bounds__(256) void k_transpose_x(const float* __restrict__ x) {
    __shared__ float s[HW_ * 130];
    const int hp = blockIdx.x, bb = blockIdx.y, tid = threadIdx.x;
    __half* dst = g_xh + ((size_t)(bb * XHW + hp) * XHW) * C_;
    if (hp == 0 || hp == XHW - 1) {
        uint4 z = make_uint4(0, 0, 0, 0);
        for (int i = tid; i < XHW * 16; i += 256) ((uint4*)dst)[i] = z;  // 8 halves each
        return;
    }
    const float* src = x + ((size_t)bb * C_) * PIX_ + (hp - 1) * HW_;
    for (int i = tid; i < C_ * 14; i += 256) {          // 14 float4 per channel row
        int c = i / 14, w4 = i - c * 14;
        float4 v = *(const float4*)(src + (size_t)c * PIX_ + w4 * 4);
        float* sc = s + (w4 * 4) * 130 + c;
        sc[0]   = v.x;
        sc[130] = v.y;
        sc[260] = v.z;
        sc[390] = v.w;
    }
    __syncthreads();
    for (int o = tid; o < XHW * 32; o += 256) {         // 4 channels -> uint2 (4 halves)
        int wp = o >> 5, c4 = (o & 31) << 2;
        uint2 hv = make_uint2(0u, 0u);
        if (wp != 0 && wp != XHW - 1) {
            const float* sr = s + (wp - 1) * 130;
            __half2 h0 = __floats2half2_rn(sr[c4 + 0], sr[c4 + 1]);
            __half2 h1 = __floats2half2_rn(sr[c4 + 2], sr[c4 + 3]);
            hv.x = *(uint32_t*)&h0;
            hv.y = *(uint32_t*)&h1;
        }
        ((uint2*)dst)[o] = hv;
    }
}

// ---------- prologue 2: W[(c*9+tap)][f] fp32 -> g_wt[tap*2+hc][f][cl] fp16 ----------
__global__ __launch_bounds__(256) void k_transpose_w(const float* __restrict__ Wg) {
    int i = blockIdx.x * 256 + threadIdx.x;
    if (i < 18 * 128 * 64) {
        int t2 = i / 8192;               // tap*2 + hc
        int r  = i - t2 * 8192;
        int f  = r >> 6;
        int cl = r & 63;
        int tap = t2 >> 1;
        int c   = ((t2 & 1) << 6) + cl;
        g_wt[i] = __float2half_rn(Wg[(c * 9 + tap) * F_ + f]);
    }
}

// ---------- main: fp16 mma + ldmatrix, 4 warps x (64x64), 3 CTAs/SM, NST=2 ----------
__global__ __launch_bounds__(128, 3)
void k_conv_main(const float* __restrict__ Di, float* __restrict__ out) {
    extern __shared__ float dynsmem[];
    uint32_t dbase = smem_u32(dynsmem);
    dbase = (dbase + 1023u) & ~1023u;

    const int tid   = threadIdx.x;
    const int lane  = tid & 31;
    const int warp  = tid >> 5;
    const int warpM = warp >> 1;   // 0..1 -> 64 rows
    const int warpN = warp & 1;    // 0..1 -> 64 cols
    const int T     = blockIdx.x;  // pixels [T*128, T*128+128)

    float acc[4][8][4];
    #pragma unroll
    for (int mt = 0; mt < 4; mt++)
        #pragma unroll
        for (int nt = 0; nt < 8; nt++)
            #pragma unroll
            for (int r = 0; r < 4; r++) acc[mt][nt][r] = 0.0f;

    // ---- cp.async A-source table (divides too costly to recompute) ----
    int srcA[8];
    #pragma unroll
    for (int i = 0; i < 8; i++) {
        int idx = tid + 128 * i;        // 0..1023
        int m = idx >> 3, g = idx & 7;
        int p = T * 128 + m;
        int bb = p / PIX_;
        int r  = p - bb * PIX_;
        int h  = r / HW_;
        int w  = r - h * HW_;
        srcA[i] = ((bb * XHW + h) * XHW + w) * 256 + g * 16;   // 256B per pixel record
    }
    const char* xh = (const char*)g_xh;
    const char* wt = (const char*)g_wt;

    // ---- ldmatrix lane geometry (offsets recomputed inline per ks) ----
    const int l7 = lane & 7;
    const int rA = l7 + ((lane >> 3) & 1) * 8;
    const int gA = lane >> 4;
    const int rB = l7 + ((lane >> 4) & 1) * 8;
    const int gB = (lane >> 3) & 1;
    uint32_t abase[4], bbase[4];
    #pragma unroll
    for (int mt = 0; mt < 4; mt++) abase[mt] = (warpM * 64 + mt * 16 + rA) * 128;
    #pragma unroll
    for (int np = 0; np < 4; np++) bbase[np] = 16384 + (warpN * 64 + np * 16 + rB) * 128;

    auto issue = [&](int s, uint32_t sb) {
        int tap = s >> 1, hc = s & 1;
        int dh = tap / 3, dw = tap - dh * 3;
        int aadd = (dh * XHW + dw) * 256 + hc * 128;
        long badd = (long)s * 16384;
        #pragma unroll
        for (int i = 0; i < 8; i++) {
            int idx = tid + 128 * i;
            int m = idx >> 3, g = idx & 7;
            uint32_t d = m * 128 + ((g ^ (m & 7)) << 4);
            CP_CG(sb + d, xh + srcA[i] + aadd);
            CP_CA(sb + 16384 + d, wt + (long)idx * 16 + badd);
        }
        CP_COMMIT();
    };

    // ---- depth-1 pipeline, 2 stages: wait(s) -> barrier -> issue(s+1) -> compute(s) ----
    uint32_t sb0 = dbase, sb1 = dbase + STAGE;
    issue(0, sb0);
    #pragma unroll 1
    for (int s = 0; s < 18; s++) {
        asm volatile("cp.async.wait_group 0;" ::: "memory");   // stage s landed
        __syncthreads();                                       // visible to all; compute(s-1) done
        if (s < 17) issue(s + 1, sb1);                         // into the stage compute(s-1) used

        #pragma unroll
        for (int ks = 0; ks < 4; ks++) {
            uint32_t oA = (uint32_t)(((2 * ks + gA) ^ l7) << 4);
            uint32_t oB = (uint32_t)(((2 * ks + gB) ^ l7) << 4);
            uint32_t a[4][4];
            #pragma unroll
            for (int mt = 0; mt < 4; mt++)
                LDSM4(a[mt][0], a[mt][1], a[mt][2], a[mt][3], sb0 + abase[mt] + oA);
            uint32_t bf[4][4];
            #pragma unroll
            for (int np = 0; np < 4; np++)
                LDSM4(bf[np][0], bf[np][1], bf[np][2], bf[np][3], sb0 + bbase[np] + oB);
            #pragma unroll
            for (int mt = 0; mt < 4; mt++)
                #pragma unroll
                for (int np = 0; np < 4; np++) {
                    mma_f16(acc[mt][2 * np + 0], a[mt], &bf[np][0]);
                    mma_f16(acc[mt][2 * np + 1], a[mt], &bf[np][2]);
                }
        }
        uint32_t t0 = sb0; sb0 = sb1; sb1 = t0;   // swap stages
    }

    // ---- epilogue: ti = min(y + 1 - Di[f], 1), NHWC float2 stores ----
    float thr[8][2];
    #pragma unroll
    for (int nt = 0; nt < 8; nt++) {
        int f = warpN * 64 + nt * 8 + 2 * (lane & 3);
        thr[nt][0] = 1.0f - Di[f];
        thr[nt][1] = 1.0f - Di[f + 1];
    }
    #pragma unroll
    for (int mt = 0; mt < 4; mt++) {
        #pragma unroll
        for (int half = 0; half < 2; half++) {
            int m = warpM * 64 + mt * 16 + half * 8 + (lane >> 2);
            int p = T * 128 + m;
            int bb = p / PIX_;
            int r  = p - bb * PIX_;
            float* op = out + ((size_t)bb * PIX_ + r) * F_;
            #pragma unroll
            for (int nt = 0; nt < 8; nt++) {
                int f = warpN * 64 + nt * 8 + 2 * (lane & 3);
                float2 vv;
                vv.x = fminf(acc[mt][nt][2 * half + 0] + thr[nt][0], 1.0f);
                vv.y = fminf(acc[mt][nt][2 * half + 1] + thr[nt][1], 1.0f);
                *(float2*)(op + f) = vv;
            }
        }
    }
}

extern "C" void kernel_launch(void* const* d_in, const int* in_sizes, int n_in,
                              void* d_out, int out_size) {
    (void)in_sizes; (void)n_in; (void)out_size;
    const float* x  = (const float*)d_in[0];
    const float* Wg = (const float*)d_in[1];
    const float* Di = (const float*)d_in[2];
    float* out = (float*)d_out;

    cudaFuncSetAttribute(k_conv_main, cudaFuncAttributeMaxDynamicSharedMemorySize, DYN);

    dim3 gx(XHW, B_);
    k_transpose_x<<<gx, 256>>>(x);
    k_transpose_w<<<(18 * 128 * 64 + 255) / 256, 256>>>(Wg);

    k_conv_main<<<784, 128, DYN>>>(Di, out);
}

// round 15
// speedup vs baseline: 1.2004x; 1.2004x over previous
#include <cuda_runtime.h>
#include <cuda_fp16.h>
#include <cstdint>

#define HW_   56
#define C_    128
#define F_    128
#define B_    32
#define PIX_  (HW_*HW_)
#define XHW   58                 // padded spatial
#define STAGE 32768              // A 16KB + B 16KB (halves, K=64 per step)
#define NST   3
#define DYN   (NST*STAGE + 1024)

// device scratch (static globals = allowed)
__device__ __half g_xh[(size_t)B_ * XHW * XHW * C_];  // [b][hp][wp][c] fp16, zero halo
__device__ __half g_wt[18 * 128 * 64];                // [tap*2+hc][f][c(64)] fp16

__device__ __forceinline__ uint32_t smem_u32(const void* p) {
    uint32_t a;
    asm("{ .reg .u64 t; cvta.to.shared.u64 t, %1; cvt.u32.u64 %0, t; }" : "=r"(a) : "l"(p));
    return a;
}
__device__ __forceinline__ void mma_f16(float d[4], const uint32_t a[4], const uint32_t b[2]) {
    asm volatile(
        "mma.sync.aligned.m16n8k16.row.col.f32.f16.f16.f32 "
        "{%0,%1,%2,%3}, {%4,%5,%6,%7}, {%8,%9}, {%0,%1,%2,%3};\n"
        : "+f"(d[0]), "+f"(d[1]), "+f"(d[2]), "+f"(d[3])
        : "r"(a[0]), "r"(a[1]), "r"(a[2]), "r"(a[3]), "r"(b[0]), "r"(b[1]));
}
#define LDSM4(r0, r1, r2, r3, a) \
    asm volatile("ldmatrix.sync.aligned.m8n8.x4.shared.b16 {%0,%1,%2,%3}, [%4];" \
                 : "=r"(r0), "=r"(r1), "=r"(r2), "=r"(r3) : "r"(a))
#define CP_CG(d, s) asm volatile("cp.async.cg.shared.global [%0], [%1], 16;" :: "r"(d), "l"(s))
#define CP_CA(d, s) asm volatile("cp.async.ca.shared.global [%0], [%1], 16;" :: "r"(d), "l"(s))
#define CP_COMMIT() asm volatile("cp.async.commit_group;" ::: "memory")

// ---------- prologue: x NCHW fp32 -> zero-padded NHWC fp16 ; W transpose slice ----------
__global__ __launch_bounds__(256) void k_transpose_x(const float* __restrict__ x,
                                                     const float* __restrict__ Wg) {
    const int bb = blockIdx.y, tid = threadIdx.x;

    if (bb == B_) {
        // ---- W transpose slice: 58 blocks cover 18*128*64 elements ----
        for (int i = blockIdx.x * 256 + tid; i < 18 * 128 * 64; i += 58 * 256) {
            int t2 = i / 8192;               // tap*2 + hc
            int r  = i - t2 * 8192;
            int f  = r >> 6;
            int cl = r & 63;
            int tap = t2 >> 1;
            int c   = ((t2 & 1) << 6) + cl;
            g_wt[i] = __float2half_rn(Wg[(c * 9 + tap) * F_ + f]);
        }
        return;
    }

    __shared__ float s[HW_ * 130];
    const int hp = blockIdx.x;
    __half* dst = g_xh + ((size_t)(bb * XHW + hp) * XHW) * C_;
    if (hp == 0 || hp == XHW - 1) {
        uint4 z = make_uint4(0, 0, 0, 0);
        for (int i = tid; i < XHW * 16; i += 256) ((uint4*)dst)[i] = z;  // 8 halves each
        return;
    }
    const float* src = x + ((size_t)bb * C_) * PIX_ + (hp - 1) * HW_;
    // phase 1: exactly 7 trips/thread (C_*14 = 1792 = 7*256) — unrolled for MLP
    #pragma unroll
    for (int k = 0; k < 7; k++) {
        int i = tid + k * 256;
        int c = i / 14, w4 = i - c * 14;
        float4 v = *(const float4*)(src + (size_t)c * PIX_ + w4 * 4);
        float* sc = s + (w4 * 4) * 130 + c;
        sc[0]   = v.x;
        sc[130] = v.y;
        sc[260] = v.z;
        sc[390] = v.w;
    }
    __syncthreads();
    // phase 2: 8 trips (XHW*32 = 1856), last guarded — unrolled
    #pragma unroll
    for (int k = 0; k < 8; k++) {
        int o = tid + k * 256;
        if (o < XHW * 32) {
            int wp = o >> 5, c4 = (o & 31) << 2;
            uint2 hv = make_uint2(0u, 0u);
            if (wp != 0 && wp != XHW - 1) {
                const float* sr = s + (wp - 1) * 130;
                __half2 h0 = __floats2half2_rn(sr[c4 + 0], sr[c4 + 1]);
                __half2 h1 = __floats2half2_rn(sr[c4 + 2], sr[c4 + 3]);
                hv.x = *(uint32_t*)&h0;
                hv.y = *(uint32_t*)&h1;
            }
            ((uint2*)dst)[o] = hv;
        }
    }
}

// ---------- main: fp16 mma.m16n8k16 + ldmatrix, 4 warps x (64x64), K=64 steps (R10) ----------
__global__ __launch_bounds__(128, 2)
void k_conv_main(const float* __restrict__ Di, float* __restrict__ out) {
    extern __shared__ float dynsmem[];
    uint32_t dbase = smem_u32(dynsmem);
    dbase = (dbase + 1023u) & ~1023u;

    const int tid   = threadIdx.x;
    const int lane  = tid & 31;
    const int warp  = tid >> 5;
    const int warpM = warp >> 1;   // 0..1 -> 64 rows
    const int warpN = warp & 1;    // 0..1 -> 64 cols
    const int T     = blockIdx.x;  // pixels [T*128, T*128+128)

    float thr[8][2];
    #pragma unroll
    for (int nt = 0; nt < 8; nt++) {
        int f = warpN * 64 + nt * 8 + 2 * (lane & 3);
        thr[nt][0] = 1.0f - Di[f];
        thr[nt][1] = 1.0f - Di[f + 1];
    }

    float acc[4][8][4];
    #pragma unroll
    for (int mt = 0; mt < 4; mt++)
        #pragma unroll
        for (int nt = 0; nt < 8; nt++)
            #pragma unroll
            for (int r = 0; r < 4; r++) acc[mt][nt][r] = 0.0f;

    // ---- cp.async tables: 8 A + 8 B 16B-copies per thread (128 thr) ----
    int srcA[8]; uint32_t dstA[8], dstB[8];
    #pragma unroll
    for (int i = 0; i < 8; i++) {
        int idx = tid + 128 * i;        // 0..1023
        int m = idx >> 3, g = idx & 7;
        int p = T * 128 + m;
        int bb = p / PIX_;
        int r  = p - bb * PIX_;
        int h  = r / HW_;
        int w  = r - h * HW_;
        srcA[i] = ((bb * XHW + h) * XHW + w) * 256 + g * 16;   // 256B per pixel (128 halves)
        dstA[i] = m * 128 + ((g ^ (m & 7)) << 4);
        dstB[i] = 16384 + dstA[i];
    }
    const char* xh = (const char*)g_xh;
    const char* wt = (const char*)g_wt;

    // ---- ldmatrix lane geometry ----
    const int l7 = lane & 7;
    const int rA = l7 + ((lane >> 3) & 1) * 8;
    const int gA = lane >> 4;
    const int rB = l7 + ((lane >> 4) & 1) * 8;
    const int gB = (lane >> 3) & 1;
    uint32_t offA[4], offB[4];
    #pragma unroll
    for (int ks = 0; ks < 4; ks++) {
        offA[ks] = (((2 * ks + gA) ^ l7) << 4);
        offB[ks] = (((2 * ks + gB) ^ l7) << 4);
    }
    uint32_t abase[4], bbase[4];
    #pragma unroll
    for (int mt = 0; mt < 4; mt++) abase[mt] = (warpM * 64 + mt * 16 + rA) * 128;
    #pragma unroll
    for (int np = 0; np < 4; np++) bbase[np] = 16384 + (warpN * 64 + np * 16 + rB) * 128;

    auto issue = [&](int s, uint32_t sb) {
        int tap = s >> 1, hc = s & 1;
        int dh = tap / 3, dw = tap - dh * 3;
        int aadd = (dh * XHW + dw) * 256 + hc * 128;
        long badd = (long)s * 16384;
        #pragma unroll
        for (int i = 0; i < 8; i++) CP_CG(sb + dstA[i], xh + srcA[i] + aadd);
        #pragma unroll
        for (int i = 0; i < 8; i++) CP_CA(sb + dstB[i], wt + (long)(tid + 128 * i) * 16 + badd);
        CP_COMMIT();
    };

    // ---- depth-2 cp.async pipeline: 18 steps of K=64 ----
    uint32_t sb0 = dbase, sb1 = dbase + STAGE, sb2 = dbase + 2 * STAGE;
    issue(0, sb0);
    issue(1, sb1);
    #pragma unroll 1
    for (int s = 0; s < 18; s++) {
        if (s < 17) { asm volatile("cp.async.wait_group 1;" ::: "memory"); }
        else        { asm volatile("cp.async.wait_group 0;" ::: "memory"); }
        __syncthreads();
        if (s < 16) issue(s + 2, sb2);

        #pragma unroll
        for (int ks = 0; ks < 4; ks++) {
            uint32_t a[4][4];
            #pragma unroll
            for (int mt = 0; mt < 4; mt++)
                LDSM4(a[mt][0], a[mt][1], a[mt][2], a[mt][3], sb0 + abase[mt] + offA[ks]);
            uint32_t bf[4][4];
            #pragma unroll
            for (int np = 0; np < 4; np++)
                LDSM4(bf[np][0], bf[np][1], bf[np][2], bf[np][3], sb0 + bbase[np] + offB[ks]);
            #pragma unroll
            for (int mt = 0; mt < 4; mt++)
                #pragma unroll
                for (int np = 0; np < 4; np++) {
                    mma_f16(acc[mt][2 * np + 0], a[mt], &bf[np][0]);
                    mma_f16(acc[mt][2 * np + 1], a[mt], &bf[np][2]);
                }
        }
        uint32_t t0 = sb0; sb0 = sb1; sb1 = sb2; sb2 = t0;   // rotate stages
    }

    // ---- epilogue: ti = min(y + 1 - Di[f], 1), NHWC float2 stores ----
    #pragma unroll
    for (int mt = 0; mt < 4; mt++) {
        #pragma unroll
        for (int half = 0; half < 2; half++) {
            int m = warpM * 64 + mt * 16 + half * 8 + (lane >> 2);
            int p = T * 128 + m;
            int bb = p / PIX_;
            int r  = p - bb * PIX_;
            float* op = out + ((size_t)bb * PIX_ + r) * F_;
            #pragma unroll
            for (int nt = 0; nt < 8; nt++) {
                int f = warpN * 64 + nt * 8 + 2 * (lane & 3);
                float2 vv;
                vv.x = fminf(acc[mt][nt][2 * half + 0] + thr[nt][0], 1.0f);
                vv.y = fminf(acc[mt][nt][2 * half + 1] + thr[nt][1], 1.0f);
                *(float2*)(op + f) = vv;
            }
        }
    }
}

extern "C" void kernel_launch(void* const* d_in, const int* in_sizes, int n_in,
                              void* d_out, int out_size) {
    (void)in_sizes; (void)n_in; (void)out_size;
    const float* x  = (const float*)d_in[0];
    const float* Wg = (const float*)d_in[1];
    const float* Di = (const float*)d_in[2];
    float* out = (float*)d_out;

    cudaFuncSetAttribute(k_conv_main, cudaFuncAttributeMaxDynamicSharedMemorySize, DYN);

    dim3 gx(XHW, B_ + 1);              // y == 32 slice does the W transpose
    k_transpose_x<<<gx, 256>>>(x, Wg);

    k_conv_main<<<784, 128, DYN>>>(Di, out);
}

// round 16
// speedup vs baseline: 1.2686x; 1.0568x over previous
#include <cuda_runtime.h>
#include <cuda_fp16.h>
#include <cstdint>

#define HW_   56
#define C_    128
#define F_    128
#define B_    32
#define PIX_  (HW_*HW_)
#define XHW   58                 // padded spatial
#define STAGE 32768              // A 16KB + B 16KB (halves, K=64 per step)
#define NST   3
#define DYN   (NST*STAGE + 1024)

// device scratch (static globals = allowed)
__device__ __half g_xh[(size_t)B_ * XHW * XHW * C_];            // [b][hp][wp][c] fp16, zero halo
__device__ __align__(16) __half g_wt[18 * 128 * 64];            // PRE-SWIZZLED B tiles, 16KB each

__device__ __forceinline__ uint32_t smem_u32(const void* p) {
    uint32_t a;
    asm("{ .reg .u64 t; cvta.to.shared.u64 t, %1; cvt.u32.u64 %0, t; }" : "=r"(a) : "l"(p));
    return a;
}
__device__ __forceinline__ void mma_f16(float d[4], const uint32_t a[4], const uint32_t b[2]) {
    asm volatile(
        "mma.sync.aligned.m16n8k16.row.col.f32.f16.f16.f32 "
        "{%0,%1,%2,%3}, {%4,%5,%6,%7}, {%8,%9}, {%0,%1,%2,%3};\n"
        : "+f"(d[0]), "+f"(d[1]), "+f"(d[2]), "+f"(d[3])
        : "r"(a[0]), "r"(a[1]), "r"(a[2]), "r"(a[3]), "r"(b[0]), "r"(b[1]));
}
#define LDSM4(r0, r1, r2, r3, a) \
    asm volatile("ldmatrix.sync.aligned.m8n8.x4.shared.b16 {%0,%1,%2,%3}, [%4];" \
                 : "=r"(r0), "=r"(r1), "=r"(r2), "=r"(r3) : "r"(a))
#define CP_CG(d, s) asm volatile("cp.async.cg.shared.global [%0], [%1], 16;" :: "r"(d), "l"(s))
#define CP_COMMIT() asm volatile("cp.async.commit_group;" ::: "memory")

#define MBAR_INIT(a, c) \
    asm volatile("mbarrier.init.shared.b64 [%0], %1;" :: "r"(a), "r"(c) : "memory")
#define MBAR_EXPECT_TX(a, b) \
    asm volatile("mbarrier.arrive.expect_tx.shared.b64 _, [%0], %1;" :: "r"(a), "r"(b) : "memory")
#define BULK_LD(dst, src, bytes, mbar) \
    asm volatile("cp.async.bulk.shared::cta.global.mbarrier::complete_tx::bytes [%0], [%1], %2, [%3];" \
                 :: "r"(dst), "l"(src), "r"(bytes), "r"(mbar) : "memory")
#define MBAR_WAIT(a, par) do {                                                   \
    uint32_t _m = (a), _p = (par), _d;                                           \
    asm volatile("{\n .reg .pred p;\n"                                           \
        " mbarrier.try_wait.parity.shared.b64 p, [%1], %2;\n"                    \
        " selp.b32 %0, 1, 0, p;\n}" : "=r"(_d) : "r"(_m), "r"(_p) : "memory");   \
    while (!_d) {                                                                \
        asm volatile("{\n .reg .pred p;\n"                                       \
            " mbarrier.try_wait.parity.shared.b64 p, [%1], %2;\n"                \
            " selp.b32 %0, 1, 0, p;\n}" : "=r"(_d) : "r"(_m), "r"(_p) : "memory"); \
    } } while (0)

// ---------- prologue: x NCHW fp32 -> zero-padded NHWC fp16 ; W transpose+swizzle slice ----------
__global__ __launch_bounds__(256) void k_transpose_x(const float* __restrict__ x,
                                                     const float* __restrict__ Wg) {
    const int bb = blockIdx.y, tid = threadIdx.x;

    if (bb == B_) {
        // W slice: logical (t2, f, cl) -> PRE-SWIZZLED dest so bulk copy lands LDSM-ready
        for (int i = blockIdx.x * 256 + tid; i < 18 * 128 * 64; i += 58 * 256) {
            int t2 = i / 8192;               // tap*2 + hc
            int r  = i - t2 * 8192;
            int f  = r >> 6;
            int cl = r & 63;
            int g  = cl >> 3, j = cl & 7;
            int tap = t2 >> 1;
            int c   = ((t2 & 1) << 6) + cl;
            int dst = t2 * 8192 + f * 64 + ((g ^ (f & 7)) << 3) + j;
            g_wt[dst] = __float2half_rn(Wg[(c * 9 + tap) * F_ + f]);
        }
        return;
    }

    __shared__ float s[HW_ * 130];
    const int hp = blockIdx.x;
    __half* dst = g_xh + ((size_t)(bb * XHW + hp) * XHW) * C_;
    if (hp == 0 || hp == XHW - 1) {
        uint4 z = make_uint4(0, 0, 0, 0);
        for (int i = tid; i < XHW * 16; i += 256) ((uint4*)dst)[i] = z;
        return;
    }
    const float* src = x + ((size_t)bb * C_) * PIX_ + (hp - 1) * HW_;
    #pragma unroll
    for (int k = 0; k < 7; k++) {
        int i = tid + k * 256;
        int c = i / 14, w4 = i - c * 14;
        float4 v = *(const float4*)(src + (size_t)c * PIX_ + w4 * 4);
        float* sc = s + (w4 * 4) * 130 + c;
        sc[0]   = v.x;
        sc[130] = v.y;
        sc[260] = v.z;
        sc[390] = v.w;
    }
    __syncthreads();
    #pragma unroll
    for (int k = 0; k < 8; k++) {
        int o = tid + k * 256;
        if (o < XHW * 32) {
            int wp = o >> 5, c4 = (o & 31) << 2;
            uint2 hv = make_uint2(0u, 0u);
            if (wp != 0 && wp != XHW - 1) {
                const float* sr = s + (wp - 1) * 130;
                __half2 h0 = __floats2half2_rn(sr[c4 + 0], sr[c4 + 1]);
                __half2 h1 = __floats2half2_rn(sr[c4 + 2], sr[c4 + 3]);
                hv.x = *(uint32_t*)&h0;
                hv.y = *(uint32_t*)&h1;
            }
            ((uint2*)dst)[o] = hv;
        }
    }
}

// ---------- main: fp16 mma + ldmatrix; A via cp.async, B via cp.async.bulk ----------
__global__ __launch_bounds__(128, 2)
void k_conv_main(const float* __restrict__ Di, float* __restrict__ out) {
    extern __shared__ float dynsmem[];
    __shared__ __align__(8) uint64_t s_mbar[NST];
    uint32_t dbase = smem_u32(dynsmem);
    dbase = (dbase + 1023u) & ~1023u;

    const int tid   = threadIdx.x;
    const int lane  = tid & 31;
    const int warp  = tid >> 5;
    const int warpM = warp >> 1;
    const int warpN = warp & 1;
    const int T     = blockIdx.x;

    uint32_t mb[NST];
    #pragma unroll
    for (int i = 0; i < NST; i++) mb[i] = smem_u32(&s_mbar[i]);
    if (tid == 0) {
        #pragma unroll
        for (int i = 0; i < NST; i++) MBAR_INIT(mb[i], 1);
    }

    float thr[8][2];
    #pragma unroll
    for (int nt = 0; nt < 8; nt++) {
        int f = warpN * 64 + nt * 8 + 2 * (lane & 3);
        thr[nt][0] = 1.0f - Di[f];
        thr[nt][1] = 1.0f - Di[f + 1];
    }

    float acc[4][8][4];
    #pragma unroll
    for (int mt = 0; mt < 4; mt++)
        #pragma unroll
        for (int nt = 0; nt < 8; nt++)
            #pragma unroll
            for (int r = 0; r < 4; r++) acc[mt][nt][r] = 0.0f;

    // ---- A cp.async tables: 8 16B-copies per thread ----
    int srcA[8]; uint32_t dstA[8];
    #pragma unroll
    for (int i = 0; i < 8; i++) {
        int idx = tid + 128 * i;
        int m = idx >> 3, g = idx & 7;
        int p = T * 128 + m;
        int bb = p / PIX_;
        int r  = p - bb * PIX_;
        int h  = r / HW_;
        int w  = r - h * HW_;
        srcA[i] = ((bb * XHW + h) * XHW + w) * 256 + g * 16;
        dstA[i] = m * 128 + ((g ^ (m & 7)) << 4);
    }
    const char* xh = (const char*)g_xh;
    const char* wt = (const char*)g_wt;

    // ---- ldmatrix lane geometry ----
    const int l7 = lane & 7;
    const int rA = l7 + ((lane >> 3) & 1) * 8;
    const int gA = lane >> 4;
    const int rB = l7 + ((lane >> 4) & 1) * 8;
    const int gB = (lane >> 3) & 1;
    uint32_t offA[4], offB[4];
    #pragma unroll
    for (int ks = 0; ks < 4; ks++) {
        offA[ks] = (((2 * ks + gA) ^ l7) << 4);
        offB[ks] = (((2 * ks + gB) ^ l7) << 4);
    }
    uint32_t abase[4], bbase[4];
    #pragma unroll
    for (int mt = 0; mt < 4; mt++) abase[mt] = (warpM * 64 + mt * 16 + rA) * 128;
    #pragma unroll
    for (int np = 0; np < 4; np++) bbase[np] = 16384 + (warpN * 64 + np * 16 + rB) * 128;

    auto issueA = [&](int s, uint32_t sb) {
        int tap = s >> 1, hc = s & 1;
        int dh = tap / 3, dw = tap - dh * 3;
        int aadd = (dh * XHW + dw) * 256 + hc * 128;
        #pragma unroll
        for (int i = 0; i < 8; i++) CP_CG(sb + dstA[i], xh + srcA[i] + aadd);
        CP_COMMIT();
    };
    auto issueB = [&](int s, uint32_t sb, uint32_t m) {
        MBAR_EXPECT_TX(m, 16384u);
        BULK_LD(sb + 16384, wt + (long)s * 16384, 16384u, m);
    };

    // ---- pipeline: A via wait_group, B via mbarrier; depth-2, 18 steps of K=64 ----
    uint32_t sb0 = dbase, sb1 = dbase + STAGE, sb2 = dbase + 2 * STAGE;
    __syncthreads();                 // mbarrier init visible
    issueA(0, sb0);
    issueA(1, sb1);
    if (tid == 0) { issueB(0, sb0, mb[0]); issueB(1, sb1, mb[1]); }
    #pragma unroll 1
    for (int s = 0; s < 18; s++) {
        if (s < 17) { asm volatile("cp.async.wait_group 1;" ::: "memory"); }
        else        { asm volatile("cp.async.wait_group 0;" ::: "memory"); }
        __syncthreads();             // A(s) visible everywhere; compute(s-1) done
        if (s < 16) {
            issueA(s + 2, sb2);
            if (tid == 0) issueB(s + 2, sb2, mb[(s + 2) % NST]);
        }
        MBAR_WAIT(mb[s % NST], (s / NST) & 1);   // B(s) landed

        #pragma unroll
        for (int ks = 0; ks < 4; ks++) {
            uint32_t a[4][4];
            #pragma unroll
            for (int mt = 0; mt < 4; mt++)
                LDSM4(a[mt][0], a[mt][1], a[mt][2], a[mt][3], sb0 + abase[mt] + offA[ks]);
            uint32_t bf[4][4];
            #pragma unroll
            for (int np = 0; np < 4; np++)
                LDSM4(bf[np][0], bf[np][1], bf[np][2], bf[np][3], sb0 + bbase[np] + offB[ks]);
            #pragma unroll
            for (int mt = 0; mt < 4; mt++)
                #pragma unroll
                for (int np = 0; np < 4; np++) {
                    mma_f16(acc[mt][2 * np + 0], a[mt], &bf[np][0]);
                    mma_f16(acc[mt][2 * np + 1], a[mt], &bf[np][2]);
                }
        }
        uint32_t t0 = sb0; sb0 = sb1; sb1 = sb2; sb2 = t0;
    }

    // ---- epilogue: ti = min(y + 1 - Di[f], 1), NHWC float2 stores ----
    #pragma unroll
    for (int mt = 0; mt < 4; mt++) {
        #pragma unroll
        for (int half = 0; half < 2; half++) {
            int m = warpM * 64 + mt * 16 + half * 8 + (lane >> 2);
            int p = T * 128 + m;
            int bb = p / PIX_;
            int r  = p - bb * PIX_;
            float* op = out + ((size_t)bb * PIX_ + r) * F_;
            #pragma unroll
            for (int nt = 0; nt < 8; nt++) {
                int f = warpN * 64 + nt * 8 + 2 * (lane & 3);
                float2 vv;
                vv.x = fminf(acc[mt][nt][2 * half + 0] + thr[nt][0], 1.0f);
                vv.y = fminf(acc[mt][nt][2 * half + 1] + thr[nt][1], 1.0f);
                *(float2*)(op + f) = vv;
            }
        }
    }
}

extern "C" void kernel_launch(void* const* d_in, const int* in_sizes, int n_in,
                              void* d_out, int out_size) {
    (void)in_sizes; (void)n_in; (void)out_size;
    const float* x  = (const float*)d_in[0];
    const float* Wg = (const float*)d_in[1];
    const float* Di = (const float*)d_in[2];
    float* out = (float*)d_out;

    cudaFuncSetAttribute(k_conv_main, cudaFuncAttributeMaxDynamicSharedMemorySize, DYN);

    dim3 gx(XHW, B_ + 1);              // y == 32 slice does the W transpose
    k_transpose_x<<<gx, 256>>>(x, Wg);

    k_conv_main<<<784, 128, DYN>>>(Di, out);
}